// round 1
// baseline (speedup 1.0000x reference)
#include <cuda_runtime.h>
#include <cuda_bf16.h>
#include <mma.h>

using namespace nvcuda;

#define T_TOK 32768
#define D_DIM 1024
#define H_DIM 2048
#define O_DIM 1024
#define NE 8
#define TOPK 4

// Scratch (allocation-free rule: __device__ globals)
__device__ float g_xn[(size_t)T_TOK * D_DIM];    // 128 MB
__device__ float g_h[(size_t)T_TOK * H_DIM];     // 256 MB
__device__ float g_gate[(size_t)T_TOK * NE];     // 1 MB

__device__ __forceinline__ float gelu_exact(float v) {
    // exact gelu: v * Phi(v)
    return v * normcdff(v);
}

// ---------------------------------------------------------------------------
// Kernel 1: fused LayerNorm + router logits + top-4 softmax gate
// one block (128 threads) per token, D = 1024 -> 8 elems/thread
// ---------------------------------------------------------------------------
__global__ void ln_router_kernel(const float* __restrict__ x,
                                 const float* __restrict__ gamma,
                                 const float* __restrict__ beta,
                                 const float* __restrict__ rw,
                                 const float* __restrict__ rb) {
    const int t = blockIdx.x;
    const int tid = threadIdx.x;  // 128
    const float* xr = x + (size_t)t * D_DIM;

    float v[8];
    float s = 0.f, ss = 0.f;
#pragma unroll
    for (int i = 0; i < 8; i++) {
        float val = xr[tid + (i << 7)];
        v[i] = val;
        s += val;
        ss += val * val;
    }
#pragma unroll
    for (int o = 16; o > 0; o >>= 1) {
        s += __shfl_down_sync(0xffffffffu, s, o);
        ss += __shfl_down_sync(0xffffffffu, ss, o);
    }
    __shared__ float wsum[4], wssq[4];
    if ((tid & 31) == 0) { wsum[tid >> 5] = s; wssq[tid >> 5] = ss; }
    __syncthreads();
    float stot = wsum[0] + wsum[1] + wsum[2] + wsum[3];
    float sstot = wssq[0] + wssq[1] + wssq[2] + wssq[3];
    const float mu = stot * (1.f / D_DIM);
    const float var = sstot * (1.f / D_DIM) - mu * mu;
    const float rstd = rsqrtf(var + 1e-5f);

    float lg[NE];
#pragma unroll
    for (int e = 0; e < NE; e++) lg[e] = 0.f;
    float* xnout = g_xn + (size_t)t * D_DIM;
#pragma unroll
    for (int i = 0; i < 8; i++) {
        int idx = tid + (i << 7);
        float xn = (v[i] - mu) * rstd * gamma[idx] + beta[idx];
        xnout[idx] = xn;
        const float* w = rw + (size_t)idx * NE;  // router_w [D, E], E contiguous
#pragma unroll
        for (int e = 0; e < NE; e++) lg[e] += xn * w[e];
    }

    __shared__ float sl[128 * NE];
#pragma unroll
    for (int e = 0; e < NE; e++) sl[tid * NE + e] = lg[e];
    __syncthreads();
    for (int st = 64; st > 0; st >>= 1) {
        if (tid < st) {
#pragma unroll
            for (int e = 0; e < NE; e++) sl[tid * NE + e] += sl[(tid + st) * NE + e];
        }
        __syncthreads();
    }

    if (tid == 0) {
        float logit[NE], gate[NE];
#pragma unroll
        for (int e = 0; e < NE; e++) { logit[e] = sl[e] + rb[e]; gate[e] = 0.f; }
        int sel[TOPK];
        float mv[TOPK];
        bool used[NE];
#pragma unroll
        for (int e = 0; e < NE; e++) used[e] = false;
#pragma unroll
        for (int k = 0; k < TOPK; k++) {
            int bi = 0;
            float bv = -3.4e38f;
#pragma unroll
            for (int e = 0; e < NE; e++) {
                if (!used[e] && logit[e] > bv) { bv = logit[e]; bi = e; }
            }
            used[bi] = true;
            sel[k] = bi;
            mv[k] = bv;
        }
        const float m = mv[0];
        float den = 0.f, ex[TOPK];
#pragma unroll
        for (int k = 0; k < TOPK; k++) { ex[k] = expf(mv[k] - m); den += ex[k]; }
#pragma unroll
        for (int k = 0; k < TOPK; k++) gate[sel[k]] = ex[k] / den;
#pragma unroll
        for (int e = 0; e < NE; e++) g_gate[(size_t)t * NE + e] = gate[e];
    }
}

// ---------------------------------------------------------------------------
// Kernel 2: tf32 tiled GEMM, BM=128 BN=128 BK=32, 8 warps (2x4), warp 64x32.
// isGemm1 != 0: Out = gelu(A @ B + bias)
// isGemm1 == 0: Out += (A @ B + bias) * gate[row]   (gate pre-offset by expert)
// All dims divide tile sizes exactly (no bounds checks).
// ---------------------------------------------------------------------------
__global__ __launch_bounds__(256) void moe_gemm_kernel(
    const float* __restrict__ A, const float* __restrict__ B,
    const float* __restrict__ bias, float* __restrict__ Out,
    const float* __restrict__ gate, int K, int N, int isGemm1) {
    __shared__ float smem[9472];        // A: 128x40 (5120) + B: 32x136 (4352)
    float* sA = smem;
    float* sB = smem + 128 * 40;

    const int tid = threadIdx.x;
    const int warp = tid >> 5;
    const int wm = warp >> 2;   // 0..1  (64-row slab)
    const int wn = warp & 3;    // 0..3  (32-col slab)
    const int m0 = blockIdx.y * 128;
    const int n0 = blockIdx.x * 128;

    wmma::fragment<wmma::accumulator, 16, 16, 8, float> acc[4][2];
#pragma unroll
    for (int i = 0; i < 4; i++)
#pragma unroll
        for (int j = 0; j < 2; j++) wmma::fill_fragment(acc[i][j], 0.f);

    const int ktiles = K >> 5;
    for (int kt = 0; kt < ktiles; kt++) {
        // stage A tile 128x32
#pragma unroll
        for (int j = 0; j < 4; j++) {
            int f = tid + j * 256;              // 1024 float4s
            int r = f >> 3, c = (f & 7) << 2;
            float4 vv = *(const float4*)(A + (size_t)(m0 + r) * K + (kt << 5) + c);
            *(float4*)(sA + r * 40 + c) = vv;
        }
        // stage B tile 32x128
#pragma unroll
        for (int j = 0; j < 4; j++) {
            int f = tid + j * 256;
            int r = f >> 5, c = (f & 31) << 2;
            float4 vv = *(const float4*)(B + (size_t)((kt << 5) + r) * N + n0 + c);
            *(float4*)(sB + r * 136 + c) = vv;
        }
        __syncthreads();

#pragma unroll
        for (int kk = 0; kk < 4; kk++) {
            wmma::fragment<wmma::matrix_a, 16, 16, 8, wmma::precision::tf32, wmma::row_major> af[4];
            wmma::fragment<wmma::matrix_b, 16, 16, 8, wmma::precision::tf32, wmma::row_major> bf[2];
#pragma unroll
            for (int mi = 0; mi < 4; mi++) {
                wmma::load_matrix_sync(af[mi], sA + (wm * 64 + mi * 16) * 40 + kk * 8, 40);
#pragma unroll
                for (int q = 0; q < af[mi].num_elements; q++)
                    af[mi].x[q] = wmma::__float_to_tf32(af[mi].x[q]);
            }
#pragma unroll
            for (int ni = 0; ni < 2; ni++) {
                wmma::load_matrix_sync(bf[ni], sB + (kk * 8) * 136 + wn * 32 + ni * 16, 136);
#pragma unroll
                for (int q = 0; q < bf[ni].num_elements; q++)
                    bf[ni].x[q] = wmma::__float_to_tf32(bf[ni].x[q]);
            }
#pragma unroll
            for (int mi = 0; mi < 4; mi++)
#pragma unroll
                for (int ni = 0; ni < 2; ni++)
                    wmma::mma_sync(acc[mi][ni], af[mi], bf[ni], acc[mi][ni]);
        }
        __syncthreads();
    }

    // epilogue: two 64-row phases, reusing smem as 64 x 132
    float* sC = smem;
    for (int p = 0; p < 2; p++) {
        if (wm == p) {
#pragma unroll
            for (int mi = 0; mi < 4; mi++)
#pragma unroll
                for (int ni = 0; ni < 2; ni++)
                    wmma::store_matrix_sync(sC + (mi * 16) * 132 + wn * 32 + ni * 16,
                                            acc[mi][ni], 132, wmma::mem_row_major);
        }
        __syncthreads();
#pragma unroll
        for (int j = 0; j < 8; j++) {
            int f = tid + j * 256;              // 2048 float4s = 64x128
            int r = f >> 5, c = (f & 31) << 2;
            int gm = m0 + p * 64 + r;
            int gn = n0 + c;
            float4 cv = *(float4*)(sC + r * 132 + c);
            float4 bv = *(const float4*)(bias + gn);
            if (isGemm1) {
                cv.x = gelu_exact(cv.x + bv.x);
                cv.y = gelu_exact(cv.y + bv.y);
                cv.z = gelu_exact(cv.z + bv.z);
                cv.w = gelu_exact(cv.w + bv.w);
                *(float4*)(Out + (size_t)gm * N + gn) = cv;
            } else {
                float g = gate[(size_t)gm * NE];
                float4 ov = *(float4*)(Out + (size_t)gm * N + gn);
                ov.x += (cv.x + bv.x) * g;
                ov.y += (cv.y + bv.y) * g;
                ov.z += (cv.z + bv.z) * g;
                ov.w += (cv.w + bv.w) * g;
                *(float4*)(Out + (size_t)gm * N + gn) = ov;
            }
        }
        __syncthreads();
    }
}

// ---------------------------------------------------------------------------
// Launch: memset y; LN+router; then per expert GEMM1(gelu) -> GEMM2(scaled acc)
// ---------------------------------------------------------------------------
extern "C" void kernel_launch(void* const* d_in, const int* in_sizes, int n_in,
                              void* d_out, int out_size) {
    const float* x     = (const float*)d_in[0];
    const float* gamma = (const float*)d_in[1];
    const float* beta  = (const float*)d_in[2];
    const float* rw    = (const float*)d_in[3];
    const float* rb    = (const float*)d_in[4];
    const float* w1    = (const float*)d_in[5];
    const float* b1    = (const float*)d_in[6];
    const float* w2    = (const float*)d_in[7];
    const float* b2    = (const float*)d_in[8];
    float* y = (float*)d_out;

    float *xn_p = nullptr, *h_p = nullptr, *gate_p = nullptr;
    cudaGetSymbolAddress((void**)&xn_p, g_xn);
    cudaGetSymbolAddress((void**)&h_p, g_h);
    cudaGetSymbolAddress((void**)&gate_p, g_gate);

    cudaMemsetAsync(d_out, 0, (size_t)T_TOK * O_DIM * sizeof(float));
    ln_router_kernel<<<T_TOK, 128>>>(x, gamma, beta, rw, rb);

    dim3 g1(H_DIM / 128, T_TOK / 128);
    dim3 g2(O_DIM / 128, T_TOK / 128);
    for (int e = 0; e < NE; e++) {
        moe_gemm_kernel<<<g1, 256>>>(xn_p, w1 + (size_t)e * D_DIM * H_DIM,
                                     b1 + (size_t)e * H_DIM, h_p,
                                     nullptr, D_DIM, H_DIM, 1);
        moe_gemm_kernel<<<g2, 256>>>(h_p, w2 + (size_t)e * H_DIM * O_DIM,
                                     b2 + (size_t)e * O_DIM, y,
                                     gate_p + e, H_DIM, O_DIM, 0);
    }
}

// round 2
// speedup vs baseline: 2.2293x; 2.2293x over previous
#include <cuda_runtime.h>
#include <mma.h>

using namespace nvcuda;

#define T_TOK 32768
#define D_DIM 1024
#define H_DIM 2048
#define O_DIM 1024
#define NE 8
#define TOPK 4
#define NPAIR (T_TOK * TOPK)            // 131072
#define MAXROWS (NPAIR + NE * 128)      // 132096 (each expert segment padded to 128)
#define MAXTILES (MAXROWS / 128)        // 1032

// ---- scratch (__device__ globals; allocation-free rule) ----
__device__ float g_xn[(size_t)T_TOK * D_DIM];        // 128 MB
__device__ float g_h[(size_t)MAXROWS * H_DIM];       // ~1.08 GB
__device__ float g_yp[(size_t)NPAIR * O_DIM];        // 512 MB
__device__ int   g_sel[NPAIR];
__device__ float g_gval[NPAIR];
__device__ int   g_cnt[NE];
__device__ int   g_fill[NE];
__device__ int   g_off[NE];
__device__ int   g_tok[MAXROWS];
__device__ int   g_pair[MAXROWS];
__device__ float g_gateS[MAXROWS];
__device__ int   g_texp[MAXTILES];

__device__ __forceinline__ float gelu_exact(float v) { return v * normcdff(v); }

__device__ __forceinline__ void cp16(float* dst, const float* src) {
    unsigned d = (unsigned)__cvta_generic_to_shared(dst);
    asm volatile("cp.async.cg.shared.global [%0], [%1], 16;\n" ::"r"(d), "l"(src));
}

// ---------------------------------------------------------------------------
// Kernel 1: LayerNorm + router logits + top-4 softmax; writes xn, sel, gval
// ---------------------------------------------------------------------------
__global__ void ln_router_kernel(const float* __restrict__ x,
                                 const float* __restrict__ gamma,
                                 const float* __restrict__ beta,
                                 const float* __restrict__ rw,
                                 const float* __restrict__ rb) {
    const int t = blockIdx.x;
    const int tid = threadIdx.x;  // 128
    const float* xr = x + (size_t)t * D_DIM;

    float v[8];
    float s = 0.f, ss = 0.f;
#pragma unroll
    for (int i = 0; i < 8; i++) {
        float val = xr[tid + (i << 7)];
        v[i] = val; s += val; ss += val * val;
    }
#pragma unroll
    for (int o = 16; o > 0; o >>= 1) {
        s += __shfl_down_sync(0xffffffffu, s, o);
        ss += __shfl_down_sync(0xffffffffu, ss, o);
    }
    __shared__ float wsum[4], wssq[4];
    if ((tid & 31) == 0) { wsum[tid >> 5] = s; wssq[tid >> 5] = ss; }
    __syncthreads();
    float stot = wsum[0] + wsum[1] + wsum[2] + wsum[3];
    float sstot = wssq[0] + wssq[1] + wssq[2] + wssq[3];
    const float mu = stot * (1.f / D_DIM);
    const float var = sstot * (1.f / D_DIM) - mu * mu;
    const float rstd = rsqrtf(var + 1e-5f);

    float lg[NE];
#pragma unroll
    for (int e = 0; e < NE; e++) lg[e] = 0.f;
    float* xnout = g_xn + (size_t)t * D_DIM;
#pragma unroll
    for (int i = 0; i < 8; i++) {
        int idx = tid + (i << 7);
        float xn = (v[i] - mu) * rstd * gamma[idx] + beta[idx];
        xnout[idx] = xn;
        const float* w = rw + (size_t)idx * NE;
#pragma unroll
        for (int e = 0; e < NE; e++) lg[e] += xn * w[e];
    }

    __shared__ float sl[128 * NE];
#pragma unroll
    for (int e = 0; e < NE; e++) sl[tid * NE + e] = lg[e];
    __syncthreads();
    for (int st = 64; st > 0; st >>= 1) {
        if (tid < st) {
#pragma unroll
            for (int e = 0; e < NE; e++) sl[tid * NE + e] += sl[(tid + st) * NE + e];
        }
        __syncthreads();
    }

    if (tid == 0) {
        float logit[NE];
#pragma unroll
        for (int e = 0; e < NE; e++) logit[e] = sl[e] + rb[e];
        int sel[TOPK]; float mv[TOPK]; bool used[NE];
#pragma unroll
        for (int e = 0; e < NE; e++) used[e] = false;
#pragma unroll
        for (int k = 0; k < TOPK; k++) {
            int bi = 0; float bv = -3.4e38f;
#pragma unroll
            for (int e = 0; e < NE; e++)
                if (!used[e] && logit[e] > bv) { bv = logit[e]; bi = e; }
            used[bi] = true; sel[k] = bi; mv[k] = bv;
        }
        const float m = mv[0];
        float den = 0.f, ex[TOPK];
#pragma unroll
        for (int k = 0; k < TOPK; k++) { ex[k] = expf(mv[k] - m); den += ex[k]; }
#pragma unroll
        for (int k = 0; k < TOPK; k++) {
            g_sel[t * TOPK + k]  = sel[k];
            g_gval[t * TOPK + k] = ex[k] / den;
        }
    }
}

// ---------------------------------------------------------------------------
// Kernel 2: per-expert pair counting (block-aggregated atomics)
// ---------------------------------------------------------------------------
__global__ void count_kernel() {
    __shared__ int hist[NE];
    const int tid = threadIdx.x;  // 512
    if (tid < NE) hist[tid] = 0;
    __syncthreads();
    int i = blockIdx.x * 512 + tid;
    if (i < NPAIR) atomicAdd(&hist[g_sel[i]], 1);
    __syncthreads();
    if (tid < NE) atomicAdd(&g_cnt[tid], hist[tid]);
}

// ---------------------------------------------------------------------------
// Kernel 3: padded prefix offsets + tile->expert map (single thread)
// ---------------------------------------------------------------------------
__global__ void offsets_kernel() {
    int off = 0, tile = 0;
    for (int e = 0; e < NE; e++) {
        g_off[e] = off;
        int tiles_e = (g_cnt[e] + 127) >> 7;
        for (int i = 0; i < tiles_e; i++) g_texp[tile++] = e;
        off += tiles_e << 7;
    }
    for (; tile < MAXTILES; tile++) g_texp[tile] = -1;
}

// ---------------------------------------------------------------------------
// Kernel 4: scatter pairs into expert-sorted slots (block-aggregated)
// ---------------------------------------------------------------------------
__global__ void scatter_kernel() {
    __shared__ int lcnt[NE], lbase[NE];
    const int tid = threadIdx.x;  // 128
    const int t = blockIdx.x * 128 + tid;
    if (tid < NE) lcnt[tid] = 0;
    __syncthreads();
    int myidx[TOPK], mye[TOPK]; float myg[TOPK];
#pragma unroll
    for (int k = 0; k < TOPK; k++) {
        int e = g_sel[t * TOPK + k];
        mye[k] = e;
        myg[k] = g_gval[t * TOPK + k];
        myidx[k] = atomicAdd(&lcnt[e], 1);
    }
    __syncthreads();
    if (tid < NE) lbase[tid] = atomicAdd(&g_fill[tid], lcnt[tid]);
    __syncthreads();
#pragma unroll
    for (int k = 0; k < TOPK; k++) {
        int pos = g_off[mye[k]] + lbase[mye[k]] + myidx[k];
        g_tok[pos]   = t;
        g_pair[pos]  = t * TOPK + k;
        g_gateS[pos] = myg[k];
    }
}

// ---------------------------------------------------------------------------
// Kernel 5: tf32 GEMM, 128x128x32 tiles, cp.async double-buffered.
// isGemm1: A rows gathered from g_xn via g_tok; Out = gelu(A@w1[e] + b1[e]) -> g_h (contiguous)
// else   : A = g_h contiguous;  g_yp[pair] = (A@w2[e] + b2[e]) * gate
// ---------------------------------------------------------------------------
__global__ __launch_bounds__(256, 2) void moe_gemm_kernel(
    const float* __restrict__ A, const float* __restrict__ B,
    const float* __restrict__ bias, float* __restrict__ Out,
    int K, int N, int isGemm1) {
    extern __shared__ float smem[];
    __shared__ int   stok[128];
    __shared__ float sgate[128];
    float* sAbuf[2] = {smem, smem + 9472};
    float* sBbuf[2] = {smem + 5120, smem + 14592};

    const int tid = threadIdx.x;
    const int warp = tid >> 5;
    const int wm = warp >> 2;
    const int wn = warp & 3;
    const int te = g_texp[blockIdx.y];
    if (te < 0) return;
    const int r0 = blockIdx.y * 128;
    const int n0 = blockIdx.x * 128;
    const float* Bp = B + (size_t)te * K * N;
    const float* biasp = bias + (size_t)te * N;

    if (isGemm1) {
        if (tid < 128) stok[tid] = g_tok[r0 + tid];
        __syncthreads();
    }

    // per-thread A/B source pointers (constant across k-tiles)
    const int ar = tid >> 3, ac = (tid & 7) << 2;
    const float* asrc[4];
#pragma unroll
    for (int j = 0; j < 4; j++) {
        int r = ar + j * 32;
        if (isGemm1) {
            int tk = stok[r]; if (tk < 0) tk = 0;
            asrc[j] = g_xn + (size_t)tk * D_DIM + ac;
        } else {
            asrc[j] = A + (size_t)(r0 + r) * K + ac;
        }
    }
    const int bc = (tid & 31) << 2;
    const float* bsrc[4];
#pragma unroll
    for (int j = 0; j < 4; j++) {
        int r = (tid >> 5) + j * 8;
        bsrc[j] = Bp + (size_t)r * N + n0 + bc;
    }

    wmma::fragment<wmma::accumulator, 16, 16, 8, float> acc[4][2];
#pragma unroll
    for (int i = 0; i < 4; i++)
#pragma unroll
        for (int j = 0; j < 2; j++) wmma::fill_fragment(acc[i][j], 0.f);

    const int ktiles = K >> 5;

#define STAGE(s, kt)                                                    \
    do {                                                                \
        float* sa_ = sAbuf[s]; float* sb_ = sBbuf[s];                   \
        _Pragma("unroll")                                               \
        for (int j = 0; j < 4; j++) {                                   \
            int r = ar + j * 32;                                        \
            cp16(sa_ + r * 40 + ac, asrc[j] + (kt) * 32);               \
        }                                                               \
        _Pragma("unroll")                                               \
        for (int j = 0; j < 4; j++) {                                   \
            int r = (tid >> 5) + j * 8;                                 \
            cp16(sb_ + r * 136 + bc, bsrc[j] + (size_t)(kt) * 32 * N);  \
        }                                                               \
        asm volatile("cp.async.commit_group;\n");                       \
    } while (0)

    STAGE(0, 0);
    for (int kt = 0; kt < ktiles; kt++) {
        int s = kt & 1;
        if (kt + 1 < ktiles) {
            STAGE(s ^ 1, kt + 1);
            asm volatile("cp.async.wait_group 1;\n");
        } else {
            asm volatile("cp.async.wait_group 0;\n");
        }
        __syncthreads();

        float* sA = sAbuf[s];
        float* sB = sBbuf[s];
#pragma unroll
        for (int kk = 0; kk < 4; kk++) {
            wmma::fragment<wmma::matrix_a, 16, 16, 8, wmma::precision::tf32, wmma::row_major> af[4];
            wmma::fragment<wmma::matrix_b, 16, 16, 8, wmma::precision::tf32, wmma::row_major> bf[2];
#pragma unroll
            for (int mi = 0; mi < 4; mi++) {
                wmma::load_matrix_sync(af[mi], sA + (wm * 64 + mi * 16) * 40 + kk * 8, 40);
#pragma unroll
                for (int q = 0; q < af[mi].num_elements; q++)
                    af[mi].x[q] = wmma::__float_to_tf32(af[mi].x[q]);
            }
#pragma unroll
            for (int ni = 0; ni < 2; ni++) {
                wmma::load_matrix_sync(bf[ni], sB + (kk * 8) * 136 + wn * 32 + ni * 16, 136);
#pragma unroll
                for (int q = 0; q < bf[ni].num_elements; q++)
                    bf[ni].x[q] = wmma::__float_to_tf32(bf[ni].x[q]);
            }
#pragma unroll
            for (int mi = 0; mi < 4; mi++)
#pragma unroll
                for (int ni = 0; ni < 2; ni++)
                    wmma::mma_sync(acc[mi][ni], af[mi], bf[ni], acc[mi][ni]);
        }
        __syncthreads();
    }
#undef STAGE

    // pair ids / gates for the scatter epilogue
    if (!isGemm1 && tid < 128) {
        stok[tid]  = g_pair[r0 + tid];
        sgate[tid] = g_gateS[r0 + tid];
    }

    // epilogue: two 64-row phases through smem (64 x 132)
    float* sC = smem;
    for (int p = 0; p < 2; p++) {
        if (wm == p) {
#pragma unroll
            for (int mi = 0; mi < 4; mi++)
#pragma unroll
                for (int ni = 0; ni < 2; ni++)
                    wmma::store_matrix_sync(sC + (mi * 16) * 132 + wn * 32 + ni * 16,
                                            acc[mi][ni], 132, wmma::mem_row_major);
        }
        __syncthreads();
#pragma unroll
        for (int j = 0; j < 8; j++) {
            int f = tid + j * 256;
            int r = f >> 5, c = (f & 31) << 2;
            int lrow = p * 64 + r;
            int gn = n0 + c;
            float4 cv = *(float4*)(sC + r * 132 + c);
            float4 bv = *(const float4*)(biasp + gn);
            if (isGemm1) {
                cv.x = gelu_exact(cv.x + bv.x);
                cv.y = gelu_exact(cv.y + bv.y);
                cv.z = gelu_exact(cv.z + bv.z);
                cv.w = gelu_exact(cv.w + bv.w);
                *(float4*)(Out + (size_t)(r0 + lrow) * N + gn) = cv;
            } else {
                int pair = stok[lrow];
                if (pair >= 0) {
                    float g = sgate[lrow];
                    float4 ov;
                    ov.x = (cv.x + bv.x) * g;
                    ov.y = (cv.y + bv.y) * g;
                    ov.z = (cv.z + bv.z) * g;
                    ov.w = (cv.w + bv.w) * g;
                    *(float4*)(Out + (size_t)pair * N + gn) = ov;
                }
            }
        }
        __syncthreads();
    }
}

// ---------------------------------------------------------------------------
// Kernel 6: combine the 4 pair contributions per token (deterministic order)
// ---------------------------------------------------------------------------
__global__ void combine_kernel(float* __restrict__ y) {
    const int i = blockIdx.x * 256 + threadIdx.x;  // over T*O/4 float4s
    const int t = i >> 8;                          // O/4 = 256
    const int c = i & 255;
    const float4* yp4 = (const float4*)g_yp;
    size_t base = (size_t)t * TOPK * 256 + c;
    float4 a = yp4[base];
    float4 b = yp4[base + 256];
    float4 d = yp4[base + 512];
    float4 e = yp4[base + 768];
    float4 s;
    s.x = a.x + b.x + d.x + e.x;
    s.y = a.y + b.y + d.y + e.y;
    s.z = a.z + b.z + d.z + e.z;
    s.w = a.w + b.w + d.w + e.w;
    ((float4*)y)[i] = s;
}

// ---------------------------------------------------------------------------
extern "C" void kernel_launch(void* const* d_in, const int* in_sizes, int n_in,
                              void* d_out, int out_size) {
    const float* x     = (const float*)d_in[0];
    const float* gamma = (const float*)d_in[1];
    const float* beta  = (const float*)d_in[2];
    const float* rw    = (const float*)d_in[3];
    const float* rb    = (const float*)d_in[4];
    const float* w1    = (const float*)d_in[5];
    const float* b1    = (const float*)d_in[6];
    const float* w2    = (const float*)d_in[7];
    const float* b2    = (const float*)d_in[8];
    float* y = (float*)d_out;

    float *xn_p = nullptr, *h_p = nullptr, *yp_p = nullptr;
    int *cnt_p = nullptr, *fill_p = nullptr, *tok_p = nullptr, *pair_p = nullptr;
    cudaGetSymbolAddress((void**)&xn_p, g_xn);
    cudaGetSymbolAddress((void**)&h_p, g_h);
    cudaGetSymbolAddress((void**)&yp_p, g_yp);
    cudaGetSymbolAddress((void**)&cnt_p, g_cnt);
    cudaGetSymbolAddress((void**)&fill_p, g_fill);
    cudaGetSymbolAddress((void**)&tok_p, g_tok);
    cudaGetSymbolAddress((void**)&pair_p, g_pair);

    static bool attr_done = false;  // idempotent host-side attribute (not device state)
    cudaFuncSetAttribute(moe_gemm_kernel,
                         cudaFuncAttributeMaxDynamicSharedMemorySize, 75776);
    (void)attr_done;

    cudaMemsetAsync(cnt_p, 0, NE * sizeof(int));
    cudaMemsetAsync(fill_p, 0, NE * sizeof(int));
    cudaMemsetAsync(tok_p, 0xFF, MAXROWS * sizeof(int));
    cudaMemsetAsync(pair_p, 0xFF, MAXROWS * sizeof(int));

    ln_router_kernel<<<T_TOK, 128>>>(x, gamma, beta, rw, rb);
    count_kernel<<<(NPAIR + 511) / 512, 512>>>();
    offsets_kernel<<<1, 1>>>();
    scatter_kernel<<<T_TOK / 128, 128>>>();

    dim3 g1(H_DIM / 128, MAXTILES);
    dim3 g2(O_DIM / 128, MAXTILES);
    moe_gemm_kernel<<<g1, 256, 75776>>>(xn_p, w1, b1, h_p, D_DIM, H_DIM, 1);
    moe_gemm_kernel<<<g2, 256, 75776>>>(h_p, w2, b2, yp_p, H_DIM, O_DIM, 0);

    combine_kernel<<<(T_TOK * O_DIM / 4) / 256, 256>>>(y);
}

// round 4
// speedup vs baseline: 4.2376x; 1.9009x over previous
#include <cuda_runtime.h>
#include <cstdint>

#define T_TOK 32768
#define D_DIM 1024
#define H_DIM 2048
#define O_DIM 1024
#define NE 8
#define TOPK 4
#define NPAIR (T_TOK * TOPK)            // 131072
#define MAXROWS (NPAIR + NE * 128)      // 132096
#define MAXTILES (MAXROWS / 128)        // 1032

#define LDA 36
#define LDB 136
#define STAGE_F (128 * LDA + 32 * LDB)  // 8960 floats per stage
#define GEMM_SMEM (2 * STAGE_F * 4)     // 71680 bytes

// ---- scratch (__device__ globals; allocation-free rule) ----
__device__ float g_xn[(size_t)T_TOK * D_DIM];
__device__ float g_h[(size_t)MAXROWS * H_DIM];
__device__ float g_yp[(size_t)NPAIR * O_DIM];
__device__ float g_w1r[(size_t)NE * D_DIM * H_DIM];
__device__ float g_w2r[(size_t)NE * H_DIM * O_DIM];
__device__ int   g_sel[NPAIR];
__device__ float g_gval[NPAIR];
__device__ int   g_cnt[NE];
__device__ int   g_fill[NE];
__device__ int   g_off[NE];
__device__ int   g_tok[MAXROWS];
__device__ int   g_pair[MAXROWS];
__device__ float g_gateS[MAXROWS];
__device__ int   g_texp[MAXTILES];

__device__ __forceinline__ float gelu_exact(float v) { return v * normcdff(v); }

__device__ __forceinline__ float tf32r(float x) {
    float r;
    asm("cvt.rna.tf32.f32 %0, %1;" : "=f"(r) : "f"(x));
    return r;
}

__device__ __forceinline__ void cp16(float* dst, const float* src) {
    unsigned d = (unsigned)__cvta_generic_to_shared(dst);
    asm volatile("cp.async.cg.shared.global [%0], [%1], 16;\n" ::"r"(d), "l"(src));
}

__device__ __forceinline__ void mma16n8k8(float* d, const uint32_t* a, const uint32_t* b) {
    asm volatile(
        "mma.sync.aligned.m16n8k8.row.col.f32.tf32.tf32.f32 "
        "{%0,%1,%2,%3}, {%4,%5,%6,%7}, {%8,%9}, {%0,%1,%2,%3};\n"
        : "+f"(d[0]), "+f"(d[1]), "+f"(d[2]), "+f"(d[3])
        : "r"(a[0]), "r"(a[1]), "r"(a[2]), "r"(a[3]), "r"(b[0]), "r"(b[1]));
}

// ---------------------------------------------------------------------------
// Kernel 0: tf32 pre-round (weights)
// ---------------------------------------------------------------------------
__global__ void round_tf32_kernel(const float* __restrict__ src,
                                  float* __restrict__ dst, int n4) {
    int i = blockIdx.x * 256 + threadIdx.x;
    if (i < n4) {
        float4 v = ((const float4*)src)[i];
        v.x = tf32r(v.x); v.y = tf32r(v.y); v.z = tf32r(v.z); v.w = tf32r(v.w);
        ((float4*)dst)[i] = v;
    }
}

// ---------------------------------------------------------------------------
// Kernel 1: LayerNorm + router logits + top-4 softmax; writes tf32-rounded xn
// ---------------------------------------------------------------------------
__global__ void ln_router_kernel(const float* __restrict__ x,
                                 const float* __restrict__ gamma,
                                 const float* __restrict__ beta,
                                 const float* __restrict__ rw,
                                 const float* __restrict__ rb) {
    const int t = blockIdx.x;
    const int tid = threadIdx.x;  // 128
    const float* xr = x + (size_t)t * D_DIM;

    float v[8];
    float s = 0.f, ss = 0.f;
#pragma unroll
    for (int i = 0; i < 8; i++) {
        float val = xr[tid + (i << 7)];
        v[i] = val; s += val; ss += val * val;
    }
#pragma unroll
    for (int o = 16; o > 0; o >>= 1) {
        s += __shfl_down_sync(0xffffffffu, s, o);
        ss += __shfl_down_sync(0xffffffffu, ss, o);
    }
    __shared__ float wsum[4], wssq[4];
    if ((tid & 31) == 0) { wsum[tid >> 5] = s; wssq[tid >> 5] = ss; }
    __syncthreads();
    float stot = wsum[0] + wsum[1] + wsum[2] + wsum[3];
    float sstot = wssq[0] + wssq[1] + wssq[2] + wssq[3];
    const float mu = stot * (1.f / D_DIM);
    const float var = sstot * (1.f / D_DIM) - mu * mu;
    const float rstd = rsqrtf(var + 1e-5f);

    float lg[NE];
#pragma unroll
    for (int e = 0; e < NE; e++) lg[e] = 0.f;
    float* xnout = g_xn + (size_t)t * D_DIM;
#pragma unroll
    for (int i = 0; i < 8; i++) {
        int idx = tid + (i << 7);
        float xn = (v[i] - mu) * rstd * gamma[idx] + beta[idx];
        xnout[idx] = tf32r(xn);           // GEMM operand, pre-rounded
        const float* w = rw + (size_t)idx * NE;
#pragma unroll
        for (int e = 0; e < NE; e++) lg[e] += xn * w[e];   // full fp32 for routing
    }

    __shared__ float sl[128 * NE];
#pragma unroll
    for (int e = 0; e < NE; e++) sl[tid * NE + e] = lg[e];
    __syncthreads();
    for (int st = 64; st > 0; st >>= 1) {
        if (tid < st) {
#pragma unroll
            for (int e = 0; e < NE; e++) sl[tid * NE + e] += sl[(tid + st) * NE + e];
        }
        __syncthreads();
    }

    if (tid == 0) {
        float logit[NE];
#pragma unroll
        for (int e = 0; e < NE; e++) logit[e] = sl[e] + rb[e];
        int sel[TOPK]; float mv[TOPK]; bool used[NE];
#pragma unroll
        for (int e = 0; e < NE; e++) used[e] = false;
#pragma unroll
        for (int k = 0; k < TOPK; k++) {
            int bi = 0; float bv = -3.4e38f;
#pragma unroll
            for (int e = 0; e < NE; e++)
                if (!used[e] && logit[e] > bv) { bv = logit[e]; bi = e; }
            used[bi] = true; sel[k] = bi; mv[k] = bv;
        }
        const float m = mv[0];
        float den = 0.f, ex[TOPK];
#pragma unroll
        for (int k = 0; k < TOPK; k++) { ex[k] = expf(mv[k] - m); den += ex[k]; }
#pragma unroll
        for (int k = 0; k < TOPK; k++) {
            g_sel[t * TOPK + k]  = sel[k];
            g_gval[t * TOPK + k] = ex[k] / den;
        }
    }
}

// ---------------------------------------------------------------------------
// Kernels 2-4: count / offsets / scatter
// ---------------------------------------------------------------------------
__global__ void count_kernel() {
    __shared__ int hist[NE];
    const int tid = threadIdx.x;  // 512
    if (tid < NE) hist[tid] = 0;
    __syncthreads();
    int i = blockIdx.x * 512 + tid;
    if (i < NPAIR) atomicAdd(&hist[g_sel[i]], 1);
    __syncthreads();
    if (tid < NE) atomicAdd(&g_cnt[tid], hist[tid]);
}

__global__ void offsets_kernel() {
    int off = 0, tile = 0;
    for (int e = 0; e < NE; e++) {
        g_off[e] = off;
        int tiles_e = (g_cnt[e] + 127) >> 7;
        for (int i = 0; i < tiles_e; i++) g_texp[tile++] = e;
        off += tiles_e << 7;
    }
    for (; tile < MAXTILES; tile++) g_texp[tile] = -1;
}

__global__ void scatter_kernel() {
    __shared__ int lcnt[NE], lbase[NE];
    const int tid = threadIdx.x;  // 128
    const int t = blockIdx.x * 128 + tid;
    if (tid < NE) lcnt[tid] = 0;
    __syncthreads();
    int myidx[TOPK], mye[TOPK]; float myg[TOPK];
#pragma unroll
    for (int k = 0; k < TOPK; k++) {
        int e = g_sel[t * TOPK + k];
        mye[k] = e;
        myg[k] = g_gval[t * TOPK + k];
        myidx[k] = atomicAdd(&lcnt[e], 1);
    }
    __syncthreads();
    if (tid < NE) lbase[tid] = atomicAdd(&g_fill[tid], lcnt[tid]);
    __syncthreads();
#pragma unroll
    for (int k = 0; k < TOPK; k++) {
        int pos = g_off[mye[k]] + lbase[mye[k]] + myidx[k];
        g_tok[pos]   = t;
        g_pair[pos]  = t * TOPK + k;
        g_gateS[pos] = myg[k];
    }
}

// ---------------------------------------------------------------------------
// Kernel 5: tf32 GEMM via raw mma.sync.m16n8k8, pre-rounded operands,
// 128x128x32 tiles, 8 warps (2x4), warp 64x32, cp.async double buffer.
// ---------------------------------------------------------------------------
__global__ __launch_bounds__(256, 2) void moe_gemm_kernel(
    const float* __restrict__ A, const float* __restrict__ B,
    const float* __restrict__ bias, float* __restrict__ Out,
    int K, int N, int isGemm1) {
    extern __shared__ float smem[];
    __shared__ int   stok[128];
    __shared__ float sgate[128];
    float* sAbuf[2] = {smem, smem + STAGE_F};
    float* sBbuf[2] = {smem + 128 * LDA, smem + STAGE_F + 128 * LDA};

    const int tid = threadIdx.x;
    const int warp = tid >> 5;
    const int lane = tid & 31;
    const int gid = lane >> 2;   // 0..7
    const int tig = lane & 3;    // 0..3
    const int wm = warp >> 2;    // 0..1
    const int wn = warp & 3;     // 0..3
    const int te = g_texp[blockIdx.y];
    if (te < 0) return;
    const int r0 = blockIdx.y * 128;
    const int n0 = blockIdx.x * 128;
    const float* Bp = B + (size_t)te * K * N;
    const float* biasp = bias + (size_t)te * N;

    if (isGemm1) {
        if (tid < 128) stok[tid] = g_tok[r0 + tid];
        __syncthreads();
    }

    // staging source pointers
    const int ar = tid >> 3, ac = (tid & 7) << 2;
    const float* asrc[4];
#pragma unroll
    for (int j = 0; j < 4; j++) {
        int r = ar + j * 32;
        if (isGemm1) {
            int tk = stok[r]; if (tk < 0) tk = 0;
            asrc[j] = g_xn + (size_t)tk * D_DIM + ac;
        } else {
            asrc[j] = A + (size_t)(r0 + r) * K + ac;
        }
    }
    const int bc = (tid & 31) << 2;
    const float* bsrc[4];
#pragma unroll
    for (int j = 0; j < 4; j++) {
        int r = (tid >> 5) + j * 8;
        bsrc[j] = Bp + (size_t)r * N + n0 + bc;
    }

    float acc[4][4][4];
#pragma unroll
    for (int mi = 0; mi < 4; mi++)
#pragma unroll
        for (int ni = 0; ni < 4; ni++)
#pragma unroll
            for (int q = 0; q < 4; q++) acc[mi][ni][q] = 0.f;

    const int ktiles = K >> 5;

#define STAGE(s, kt)                                                     \
    do {                                                                 \
        float* sa_ = sAbuf[s]; float* sb_ = sBbuf[s];                    \
        _Pragma("unroll")                                                \
        for (int j = 0; j < 4; j++) {                                    \
            int r = ar + j * 32;                                         \
            cp16(sa_ + r * LDA + ac, asrc[j] + (kt) * 32);               \
        }                                                                \
        _Pragma("unroll")                                                \
        for (int j = 0; j < 4; j++) {                                    \
            int r = (tid >> 5) + j * 8;                                  \
            cp16(sb_ + r * LDB + bc, bsrc[j] + (size_t)(kt) * 32 * N);   \
        }                                                                \
        asm volatile("cp.async.commit_group;\n");                        \
    } while (0)

    STAGE(0, 0);
    for (int kt = 0; kt < ktiles; kt++) {
        int s = kt & 1;
        if (kt + 1 < ktiles) {
            STAGE(s ^ 1, kt + 1);
            asm volatile("cp.async.wait_group 1;\n");
        } else {
            asm volatile("cp.async.wait_group 0;\n");
        }
        __syncthreads();

        const float* sA = sAbuf[s];
        const float* sB = sBbuf[s];
#pragma unroll
        for (int ks = 0; ks < 4; ks++) {
            uint32_t afr[4][4];
#pragma unroll
            for (int mi = 0; mi < 4; mi++) {
                int rr = wm * 64 + mi * 16 + gid;
                int cc = ks * 8 + tig;
                afr[mi][0] = __float_as_uint(sA[rr * LDA + cc]);
                afr[mi][1] = __float_as_uint(sA[(rr + 8) * LDA + cc]);
                afr[mi][2] = __float_as_uint(sA[rr * LDA + cc + 4]);
                afr[mi][3] = __float_as_uint(sA[(rr + 8) * LDA + cc + 4]);
            }
            uint32_t bfr[4][2];
#pragma unroll
            for (int ni = 0; ni < 4; ni++) {
                int kr = ks * 8 + tig;
                int cc = wn * 32 + ni * 8 + gid;
                bfr[ni][0] = __float_as_uint(sB[kr * LDB + cc]);
                bfr[ni][1] = __float_as_uint(sB[(kr + 4) * LDB + cc]);
            }
#pragma unroll
            for (int mi = 0; mi < 4; mi++)
#pragma unroll
                for (int ni = 0; ni < 4; ni++)
                    mma16n8k8(acc[mi][ni], afr[mi], bfr[ni]);
        }
        __syncthreads();
    }
#undef STAGE

    if (!isGemm1 && tid < 128) {
        stok[tid]  = g_pair[r0 + tid];
        sgate[tid] = g_gateS[r0 + tid];
    }

    // epilogue: two 64-row phases via smem (64 x 132)
    float* sC = smem;
    for (int p = 0; p < 2; p++) {
        if (wm == p) {
#pragma unroll
            for (int mi = 0; mi < 4; mi++)
#pragma unroll
                for (int ni = 0; ni < 4; ni++) {
                    int rr = mi * 16 + gid;
                    int cc = wn * 32 + ni * 8 + 2 * tig;
                    sC[rr * 132 + cc]           = acc[mi][ni][0];
                    sC[rr * 132 + cc + 1]       = acc[mi][ni][1];
                    sC[(rr + 8) * 132 + cc]     = acc[mi][ni][2];
                    sC[(rr + 8) * 132 + cc + 1] = acc[mi][ni][3];
                }
        }
        __syncthreads();
#pragma unroll
        for (int j = 0; j < 8; j++) {
            int f = tid + j * 256;
            int r = f >> 5, c = (f & 31) << 2;
            int lrow = p * 64 + r;
            int gn = n0 + c;
            float4 cv = *(float4*)(sC + r * 132 + c);
            float4 bv = *(const float4*)(biasp + gn);
            if (isGemm1) {
                cv.x = tf32r(gelu_exact(cv.x + bv.x));
                cv.y = tf32r(gelu_exact(cv.y + bv.y));
                cv.z = tf32r(gelu_exact(cv.z + bv.z));
                cv.w = tf32r(gelu_exact(cv.w + bv.w));
                *(float4*)(Out + (size_t)(r0 + lrow) * N + gn) = cv;
            } else {
                int pair = stok[lrow];
                if (pair >= 0) {
                    float g = sgate[lrow];
                    float4 ov;
                    ov.x = (cv.x + bv.x) * g;
                    ov.y = (cv.y + bv.y) * g;
                    ov.z = (cv.z + bv.z) * g;
                    ov.w = (cv.w + bv.w) * g;
                    *(float4*)(Out + (size_t)pair * N + gn) = ov;
                }
            }
        }
        __syncthreads();
    }
}

// ---------------------------------------------------------------------------
// Kernel 6: combine 4 pair contributions per token (fixed order)
// ---------------------------------------------------------------------------
__global__ void combine_kernel(float* __restrict__ y) {
    const int i = blockIdx.x * 256 + threadIdx.x;
    const int t = i >> 8;
    const int c = i & 255;
    const float4* yp4 = (const float4*)g_yp;
    size_t bidx = (size_t)t * TOPK * 256 + c;
    float4 a = yp4[bidx];
    float4 b = yp4[bidx + 256];
    float4 d = yp4[bidx + 512];
    float4 e = yp4[bidx + 768];
    float4 s;
    s.x = a.x + b.x + d.x + e.x;
    s.y = a.y + b.y + d.y + e.y;
    s.z = a.z + b.z + d.z + e.z;
    s.w = a.w + b.w + d.w + e.w;
    ((float4*)y)[i] = s;
}

// ---------------------------------------------------------------------------
extern "C" void kernel_launch(void* const* d_in, const int* in_sizes, int n_in,
                              void* d_out, int out_size) {
    const float* x     = (const float*)d_in[0];
    const float* gamma = (const float*)d_in[1];
    const float* beta  = (const float*)d_in[2];
    const float* rw    = (const float*)d_in[3];
    const float* rb    = (const float*)d_in[4];
    const float* w1    = (const float*)d_in[5];
    const float* b1    = (const float*)d_in[6];
    const float* w2    = (const float*)d_in[7];
    const float* b2    = (const float*)d_in[8];
    float* y = (float*)d_out;

    float *xn_p = nullptr, *h_p = nullptr, *yp_p = nullptr, *w1r_p = nullptr, *w2r_p = nullptr;
    int *cnt_p = nullptr, *fill_p = nullptr, *tok_p = nullptr, *pair_p = nullptr;
    cudaGetSymbolAddress((void**)&xn_p, g_xn);
    cudaGetSymbolAddress((void**)&h_p, g_h);
    cudaGetSymbolAddress((void**)&yp_p, g_yp);
    cudaGetSymbolAddress((void**)&w1r_p, g_w1r);
    cudaGetSymbolAddress((void**)&w2r_p, g_w2r);
    cudaGetSymbolAddress((void**)&cnt_p, g_cnt);
    cudaGetSymbolAddress((void**)&fill_p, g_fill);
    cudaGetSymbolAddress((void**)&tok_p, g_tok);
    cudaGetSymbolAddress((void**)&pair_p, g_pair);

    cudaFuncSetAttribute(moe_gemm_kernel,
                         cudaFuncAttributeMaxDynamicSharedMemorySize, GEMM_SMEM);

    cudaMemsetAsync(cnt_p, 0, NE * sizeof(int));
    cudaMemsetAsync(fill_p, 0, NE * sizeof(int));
    cudaMemsetAsync(tok_p, 0xFF, MAXROWS * sizeof(int));
    cudaMemsetAsync(pair_p, 0xFF, MAXROWS * sizeof(int));

    const int W1_4 = NE * D_DIM * H_DIM / 4;
    const int W2_4 = NE * H_DIM * O_DIM / 4;
    round_tf32_kernel<<<(W1_4 + 255) / 256, 256>>>(w1, w1r_p, W1_4);
    round_tf32_kernel<<<(W2_4 + 255) / 256, 256>>>(w2, w2r_p, W2_4);

    ln_router_kernel<<<T_TOK, 128>>>(x, gamma, beta, rw, rb);
    count_kernel<<<(NPAIR + 511) / 512, 512>>>();
    offsets_kernel<<<1, 1>>>();
    scatter_kernel<<<T_TOK / 128, 128>>>();

    dim3 g1(H_DIM / 128, MAXTILES);
    dim3 g2(O_DIM / 128, MAXTILES);
    moe_gemm_kernel<<<g1, 256, GEMM_SMEM>>>(xn_p, w1r_p, b1, h_p, D_DIM, H_DIM, 1);
    moe_gemm_kernel<<<g2, 256, GEMM_SMEM>>>(h_p, w2r_p, b2, yp_p, H_DIM, O_DIM, 0);

    combine_kernel<<<(T_TOK * O_DIM / 4) / 256, 256>>>(y);
}

// round 5
// speedup vs baseline: 4.5191x; 1.0664x over previous
#include <cuda_runtime.h>
#include <cstdint>

#define T_TOK 32768
#define D_DIM 1024
#define H_DIM 2048
#define O_DIM 1024
#define NE 8
#define TOPK 4
#define NPAIR (T_TOK * TOPK)            // 131072
#define MAXROWS (NPAIR + NE * 128)      // 132096
#define MAXTILES (MAXROWS / 128)        // 1032

#define LDA 36
#define LDB 136
#define STAGE_F (128 * LDA + 32 * LDB)  // 8960 floats per stage
#define GEMM_SMEM (2 * STAGE_F * 4)     // 71680 bytes

// ---- scratch (__device__ globals; allocation-free rule) ----
__device__ float g_xn[(size_t)T_TOK * D_DIM];
__device__ float g_h[(size_t)MAXROWS * H_DIM];
__device__ float g_yp[(size_t)NPAIR * O_DIM];
__device__ float g_w1r[(size_t)NE * D_DIM * H_DIM];
__device__ float g_w2r[(size_t)NE * H_DIM * O_DIM];
__device__ int   g_sel[NPAIR];
__device__ float g_gval[NPAIR];
__device__ int   g_cnt[NE];
__device__ int   g_fill[NE];
__device__ int   g_off[NE];
__device__ int   g_tok[MAXROWS];
__device__ int   g_pair[MAXROWS];
__device__ float g_gateS[MAXROWS];
__device__ int   g_texp[MAXTILES];

__device__ __forceinline__ float gelu_exact(float v) { return v * normcdff(v); }

__device__ __forceinline__ float tf32r(float x) {
    float r;
    asm("cvt.rna.tf32.f32 %0, %1;" : "=f"(r) : "f"(x));
    return r;
}

__device__ __forceinline__ void cp16(float* dst, const float* src) {
    unsigned d = (unsigned)__cvta_generic_to_shared(dst);
    asm volatile("cp.async.cg.shared.global [%0], [%1], 16;\n" ::"r"(d), "l"(src));
}

__device__ __forceinline__ void mma16n8k8(float* d, const uint32_t* a, const uint32_t* b) {
    asm volatile(
        "mma.sync.aligned.m16n8k8.row.col.f32.tf32.tf32.f32 "
        "{%0,%1,%2,%3}, {%4,%5,%6,%7}, {%8,%9}, {%0,%1,%2,%3};\n"
        : "+f"(d[0]), "+f"(d[1]), "+f"(d[2]), "+f"(d[3])
        : "r"(a[0]), "r"(a[1]), "r"(a[2]), "r"(a[3]), "r"(b[0]), "r"(b[1]));
}

// ---------------------------------------------------------------------------
// Kernel 0: tf32 pre-round (weights)
// ---------------------------------------------------------------------------
__global__ void round_tf32_kernel(const float* __restrict__ src,
                                  float* __restrict__ dst, int n4) {
    int i = blockIdx.x * 256 + threadIdx.x;
    if (i < n4) {
        float4 v = ((const float4*)src)[i];
        v.x = tf32r(v.x); v.y = tf32r(v.y); v.z = tf32r(v.z); v.w = tf32r(v.w);
        ((float4*)dst)[i] = v;
    }
}

// ---------------------------------------------------------------------------
// Kernel 1: LayerNorm + router logits + top-4 softmax; writes tf32-rounded xn
// ---------------------------------------------------------------------------
__global__ void ln_router_kernel(const float* __restrict__ x,
                                 const float* __restrict__ gamma,
                                 const float* __restrict__ beta,
                                 const float* __restrict__ rw,
                                 const float* __restrict__ rb) {
    const int t = blockIdx.x;
    const int tid = threadIdx.x;  // 128
    const float* xr = x + (size_t)t * D_DIM;

    float v[8];
    float s = 0.f, ss = 0.f;
#pragma unroll
    for (int i = 0; i < 8; i++) {
        float val = xr[tid + (i << 7)];
        v[i] = val; s += val; ss += val * val;
    }
#pragma unroll
    for (int o = 16; o > 0; o >>= 1) {
        s += __shfl_down_sync(0xffffffffu, s, o);
        ss += __shfl_down_sync(0xffffffffu, ss, o);
    }
    __shared__ float wsum[4], wssq[4];
    if ((tid & 31) == 0) { wsum[tid >> 5] = s; wssq[tid >> 5] = ss; }
    __syncthreads();
    float stot = wsum[0] + wsum[1] + wsum[2] + wsum[3];
    float sstot = wssq[0] + wssq[1] + wssq[2] + wssq[3];
    const float mu = stot * (1.f / D_DIM);
    const float var = sstot * (1.f / D_DIM) - mu * mu;
    const float rstd = rsqrtf(var + 1e-5f);

    float lg[NE];
#pragma unroll
    for (int e = 0; e < NE; e++) lg[e] = 0.f;
    float* xnout = g_xn + (size_t)t * D_DIM;
#pragma unroll
    for (int i = 0; i < 8; i++) {
        int idx = tid + (i << 7);
        float xn = (v[i] - mu) * rstd * gamma[idx] + beta[idx];
        xnout[idx] = tf32r(xn);           // GEMM operand, pre-rounded
        const float* w = rw + (size_t)idx * NE;
#pragma unroll
        for (int e = 0; e < NE; e++) lg[e] += xn * w[e];   // full fp32 for routing
    }

    __shared__ float sl[128 * NE];
#pragma unroll
    for (int e = 0; e < NE; e++) sl[tid * NE + e] = lg[e];
    __syncthreads();
    for (int st = 64; st > 0; st >>= 1) {
        if (tid < st) {
#pragma unroll
            for (int e = 0; e < NE; e++) sl[tid * NE + e] += sl[(tid + st) * NE + e];
        }
        __syncthreads();
    }

    if (tid == 0) {
        float logit[NE];
#pragma unroll
        for (int e = 0; e < NE; e++) logit[e] = sl[e] + rb[e];
        int sel[TOPK]; float mv[TOPK]; bool used[NE];
#pragma unroll
        for (int e = 0; e < NE; e++) used[e] = false;
#pragma unroll
        for (int k = 0; k < TOPK; k++) {
            int bi = 0; float bv = -3.4e38f;
#pragma unroll
            for (int e = 0; e < NE; e++)
                if (!used[e] && logit[e] > bv) { bv = logit[e]; bi = e; }
            used[bi] = true; sel[k] = bi; mv[k] = bv;
        }
        const float m = mv[0];
        float den = 0.f, ex[TOPK];
#pragma unroll
        for (int k = 0; k < TOPK; k++) { ex[k] = expf(mv[k] - m); den += ex[k]; }
#pragma unroll
        for (int k = 0; k < TOPK; k++) {
            g_sel[t * TOPK + k]  = sel[k];
            g_gval[t * TOPK + k] = ex[k] / den;
        }
    }
}

// ---------------------------------------------------------------------------
// Kernels 2-4: count / offsets / scatter
// ---------------------------------------------------------------------------
__global__ void count_kernel() {
    __shared__ int hist[NE];
    const int tid = threadIdx.x;  // 512
    if (tid < NE) hist[tid] = 0;
    __syncthreads();
    int i = blockIdx.x * 512 + tid;
    if (i < NPAIR) atomicAdd(&hist[g_sel[i]], 1);
    __syncthreads();
    if (tid < NE) atomicAdd(&g_cnt[tid], hist[tid]);
}

__global__ void offsets_kernel() {
    int off = 0, tile = 0;
    for (int e = 0; e < NE; e++) {
        g_off[e] = off;
        int tiles_e = (g_cnt[e] + 127) >> 7;
        for (int i = 0; i < tiles_e; i++) g_texp[tile++] = e;
        off += tiles_e << 7;
    }
    for (; tile < MAXTILES; tile++) g_texp[tile] = -1;
}

__global__ void scatter_kernel() {
    __shared__ int lcnt[NE], lbase[NE];
    const int tid = threadIdx.x;  // 128
    const int t = blockIdx.x * 128 + tid;
    if (tid < NE) lcnt[tid] = 0;
    __syncthreads();
    int myidx[TOPK], mye[TOPK]; float myg[TOPK];
#pragma unroll
    for (int k = 0; k < TOPK; k++) {
        int e = g_sel[t * TOPK + k];
        mye[k] = e;
        myg[k] = g_gval[t * TOPK + k];
        myidx[k] = atomicAdd(&lcnt[e], 1);
    }
    __syncthreads();
    if (tid < NE) lbase[tid] = atomicAdd(&g_fill[tid], lcnt[tid]);
    __syncthreads();
#pragma unroll
    for (int k = 0; k < TOPK; k++) {
        int pos = g_off[mye[k]] + lbase[mye[k]] + myidx[k];
        g_tok[pos]   = t;
        g_pair[pos]  = t * TOPK + k;
        g_gateS[pos] = myg[k];
    }
}

// ---------------------------------------------------------------------------
// Kernel 5: tf32 GEMM via raw mma.sync.m16n8k8, 128x128x32 CTA tile,
// 4 warps (2x2), warp tile 64x64 (mi=4, ni=8), cp.async double buffer.
// ---------------------------------------------------------------------------
__global__ __launch_bounds__(128, 2) void moe_gemm_kernel(
    const float* __restrict__ A, const float* __restrict__ B,
    const float* __restrict__ bias, float* __restrict__ Out,
    int K, int N, int isGemm1) {
    extern __shared__ float smem[];
    __shared__ int   stok[128];
    __shared__ float sgate[128];
    float* sAbuf[2] = {smem, smem + STAGE_F};
    float* sBbuf[2] = {smem + 128 * LDA, smem + STAGE_F + 128 * LDA};

    const int tid = threadIdx.x;     // 128
    const int warp = tid >> 5;       // 0..3
    const int lane = tid & 31;
    const int gid = lane >> 2;       // 0..7
    const int tig = lane & 3;        // 0..3
    const int wm = warp >> 1;        // 0..1 (64-row slab)
    const int wn = warp & 1;         // 0..1 (64-col slab)
    const int te = g_texp[blockIdx.y];
    if (te < 0) return;
    const int r0 = blockIdx.y * 128;
    const int n0 = blockIdx.x * 128;
    const float* Bp = B + (size_t)te * K * N;
    const float* biasp = bias + (size_t)te * N;

    if (isGemm1) {
        stok[tid] = g_tok[r0 + tid];
        __syncthreads();
    }

    // staging source pointers: A 128x32 (8 float4/thread), B 32x128 (8 float4/thread)
    const int ar = tid >> 3, ac = (tid & 7) << 2;
    const float* asrc[8];
#pragma unroll
    for (int j = 0; j < 8; j++) {
        int r = ar + j * 16;
        if (isGemm1) {
            int tk = stok[r]; if (tk < 0) tk = 0;
            asrc[j] = g_xn + (size_t)tk * D_DIM + ac;
        } else {
            asrc[j] = A + (size_t)(r0 + r) * K + ac;
        }
    }
    const int bc = (tid & 31) << 2;
    const float* bsrc[8];
#pragma unroll
    for (int j = 0; j < 8; j++) {
        int r = (tid >> 5) + j * 4;
        bsrc[j] = Bp + (size_t)r * N + n0 + bc;
    }

    float acc[4][8][4];
#pragma unroll
    for (int mi = 0; mi < 4; mi++)
#pragma unroll
        for (int ni = 0; ni < 8; ni++)
#pragma unroll
            for (int q = 0; q < 4; q++) acc[mi][ni][q] = 0.f;

    const int ktiles = K >> 5;

#define STAGE(s, kt)                                                     \
    do {                                                                 \
        float* sa_ = sAbuf[s]; float* sb_ = sBbuf[s];                    \
        _Pragma("unroll")                                                \
        for (int j = 0; j < 8; j++) {                                    \
            int r = ar + j * 16;                                         \
            cp16(sa_ + r * LDA + ac, asrc[j] + (kt) * 32);               \
        }                                                                \
        _Pragma("unroll")                                                \
        for (int j = 0; j < 8; j++) {                                    \
            int r = (tid >> 5) + j * 4;                                  \
            cp16(sb_ + r * LDB + bc, bsrc[j] + (size_t)(kt) * 32 * N);   \
        }                                                                \
        asm volatile("cp.async.commit_group;\n");                        \
    } while (0)

    STAGE(0, 0);
    for (int kt = 0; kt < ktiles; kt++) {
        int s = kt & 1;
        if (kt + 1 < ktiles) {
            STAGE(s ^ 1, kt + 1);
            asm volatile("cp.async.wait_group 1;\n");
        } else {
            asm volatile("cp.async.wait_group 0;\n");
        }
        __syncthreads();

        const float* sA = sAbuf[s];
        const float* sB = sBbuf[s];
#pragma unroll
        for (int ks = 0; ks < 4; ks++) {
            uint32_t afr[4][4];
#pragma unroll
            for (int mi = 0; mi < 4; mi++) {
                int rr = wm * 64 + mi * 16 + gid;
                int cc = ks * 8 + tig;
                afr[mi][0] = __float_as_uint(sA[rr * LDA + cc]);
                afr[mi][1] = __float_as_uint(sA[(rr + 8) * LDA + cc]);
                afr[mi][2] = __float_as_uint(sA[rr * LDA + cc + 4]);
                afr[mi][3] = __float_as_uint(sA[(rr + 8) * LDA + cc + 4]);
            }
            uint32_t bfr[8][2];
#pragma unroll
            for (int ni = 0; ni < 8; ni++) {
                int kr = ks * 8 + tig;
                int cc = wn * 64 + ni * 8 + gid;
                bfr[ni][0] = __float_as_uint(sB[kr * LDB + cc]);
                bfr[ni][1] = __float_as_uint(sB[(kr + 4) * LDB + cc]);
            }
#pragma unroll
            for (int mi = 0; mi < 4; mi++)
#pragma unroll
                for (int ni = 0; ni < 8; ni++)
                    mma16n8k8(acc[mi][ni], afr[mi], bfr[ni]);
        }
        __syncthreads();
    }
#undef STAGE

    if (!isGemm1) {
        stok[tid]  = g_pair[r0 + tid];
        sgate[tid] = g_gateS[r0 + tid];
    }

    // epilogue: two 64-row phases via smem (64 x 132)
    float* sC = smem;
    for (int p = 0; p < 2; p++) {
        if (wm == p) {
#pragma unroll
            for (int mi = 0; mi < 4; mi++)
#pragma unroll
                for (int ni = 0; ni < 8; ni++) {
                    int rr = mi * 16 + gid;
                    int cc = wn * 64 + ni * 8 + 2 * tig;
                    sC[rr * 132 + cc]           = acc[mi][ni][0];
                    sC[rr * 132 + cc + 1]       = acc[mi][ni][1];
                    sC[(rr + 8) * 132 + cc]     = acc[mi][ni][2];
                    sC[(rr + 8) * 132 + cc + 1] = acc[mi][ni][3];
                }
        }
        __syncthreads();
#pragma unroll
        for (int j = 0; j < 16; j++) {
            int f = tid + j * 128;               // 2048 float4s = 64x128
            int r = f >> 5, c = (f & 31) << 2;
            int lrow = p * 64 + r;
            int gn = n0 + c;
            float4 cv = *(float4*)(sC + r * 132 + c);
            float4 bv = *(const float4*)(biasp + gn);
            if (isGemm1) {
                cv.x = tf32r(gelu_exact(cv.x + bv.x));
                cv.y = tf32r(gelu_exact(cv.y + bv.y));
                cv.z = tf32r(gelu_exact(cv.z + bv.z));
                cv.w = tf32r(gelu_exact(cv.w + bv.w));
                *(float4*)(Out + (size_t)(r0 + lrow) * N + gn) = cv;
            } else {
                int pair = stok[lrow];
                if (pair >= 0) {
                    float g = sgate[lrow];
                    float4 ov;
                    ov.x = (cv.x + bv.x) * g;
                    ov.y = (cv.y + bv.y) * g;
                    ov.z = (cv.z + bv.z) * g;
                    ov.w = (cv.w + bv.w) * g;
                    *(float4*)(Out + (size_t)pair * N + gn) = ov;
                }
            }
        }
        __syncthreads();
    }
}

// ---------------------------------------------------------------------------
// Kernel 6: combine 4 pair contributions per token (fixed order)
// ---------------------------------------------------------------------------
__global__ void combine_kernel(float* __restrict__ y) {
    const int i = blockIdx.x * 256 + threadIdx.x;
    const int t = i >> 8;
    const int c = i & 255;
    const float4* yp4 = (const float4*)g_yp;
    size_t bidx = (size_t)t * TOPK * 256 + c;
    float4 a = yp4[bidx];
    float4 b = yp4[bidx + 256];
    float4 d = yp4[bidx + 512];
    float4 e = yp4[bidx + 768];
    float4 s;
    s.x = a.x + b.x + d.x + e.x;
    s.y = a.y + b.y + d.y + e.y;
    s.z = a.z + b.z + d.z + e.z;
    s.w = a.w + b.w + d.w + e.w;
    ((float4*)y)[i] = s;
}

// ---------------------------------------------------------------------------
extern "C" void kernel_launch(void* const* d_in, const int* in_sizes, int n_in,
                              void* d_out, int out_size) {
    const float* x     = (const float*)d_in[0];
    const float* gamma = (const float*)d_in[1];
    const float* beta  = (const float*)d_in[2];
    const float* rw    = (const float*)d_in[3];
    const float* rb    = (const float*)d_in[4];
    const float* w1    = (const float*)d_in[5];
    const float* b1    = (const float*)d_in[6];
    const float* w2    = (const float*)d_in[7];
    const float* b2    = (const float*)d_in[8];
    float* y = (float*)d_out;

    float *xn_p = nullptr, *h_p = nullptr, *yp_p = nullptr, *w1r_p = nullptr, *w2r_p = nullptr;
    int *cnt_p = nullptr, *fill_p = nullptr, *tok_p = nullptr, *pair_p = nullptr;
    cudaGetSymbolAddress((void**)&xn_p, g_xn);
    cudaGetSymbolAddress((void**)&h_p, g_h);
    cudaGetSymbolAddress((void**)&yp_p, g_yp);
    cudaGetSymbolAddress((void**)&w1r_p, g_w1r);
    cudaGetSymbolAddress((void**)&w2r_p, g_w2r);
    cudaGetSymbolAddress((void**)&cnt_p, g_cnt);
    cudaGetSymbolAddress((void**)&fill_p, g_fill);
    cudaGetSymbolAddress((void**)&tok_p, g_tok);
    cudaGetSymbolAddress((void**)&pair_p, g_pair);

    cudaFuncSetAttribute(moe_gemm_kernel,
                         cudaFuncAttributeMaxDynamicSharedMemorySize, GEMM_SMEM);

    cudaMemsetAsync(cnt_p, 0, NE * sizeof(int));
    cudaMemsetAsync(fill_p, 0, NE * sizeof(int));
    cudaMemsetAsync(tok_p, 0xFF, MAXROWS * sizeof(int));
    cudaMemsetAsync(pair_p, 0xFF, MAXROWS * sizeof(int));

    const int W1_4 = NE * D_DIM * H_DIM / 4;
    const int W2_4 = NE * H_DIM * O_DIM / 4;
    round_tf32_kernel<<<(W1_4 + 255) / 256, 256>>>(w1, w1r_p, W1_4);
    round_tf32_kernel<<<(W2_4 + 255) / 256, 256>>>(w2, w2r_p, W2_4);

    ln_router_kernel<<<T_TOK, 128>>>(x, gamma, beta, rw, rb);
    count_kernel<<<(NPAIR + 511) / 512, 512>>>();
    offsets_kernel<<<1, 1>>>();
    scatter_kernel<<<T_TOK / 128, 128>>>();

    dim3 g1(H_DIM / 128, MAXTILES);
    dim3 g2(O_DIM / 128, MAXTILES);
    moe_gemm_kernel<<<g1, 128, GEMM_SMEM>>>(xn_p, w1r_p, b1, h_p, D_DIM, H_DIM, 1);
    moe_gemm_kernel<<<g2, 128, GEMM_SMEM>>>(h_p, w2r_p, b2, yp_p, H_DIM, O_DIM, 0);

    combine_kernel<<<(T_TOK * O_DIM / 4) / 256, 256>>>(y);
}

// round 6
// speedup vs baseline: 7.7801x; 1.7216x over previous
#include <cuda_runtime.h>
#include <cuda_fp16.h>
#include <cstdint>

#define T_TOK 32768
#define D_DIM 1024
#define H_DIM 2048
#define O_DIM 1024
#define NE 8
#define TOPK 4
#define NPAIR (T_TOK * TOPK)            // 131072
#define MAXROWS (NPAIR + NE * 128)      // 132096
#define MAXTILES (MAXROWS / 128)        // 1032

#define LDAH 40                          // halves per smem row (32 + 8 pad)
#define STAGE_H (2 * 128 * LDAH)         // 10240 halves per stage (A+B)
#define GEMM_SMEM (2 * STAGE_H * 2)      // 40960 bytes

// ---- scratch (__device__ globals; allocation-free rule) ----
__device__ __half g_xnh[(size_t)T_TOK * D_DIM];          // 64 MB
__device__ __half g_hh[(size_t)MAXROWS * H_DIM];         // 516 MB
__device__ float  g_yp[(size_t)NPAIR * O_DIM];           // 512 MB
__device__ __half g_w1t[(size_t)NE * H_DIM * D_DIM];     // [E][H][D] 32 MB
__device__ __half g_w2t[(size_t)NE * O_DIM * H_DIM];     // [E][O][H] 32 MB
__device__ int    g_sel[NPAIR];
__device__ float  g_gval[NPAIR];
__device__ int    g_cnt[NE];
__device__ int    g_fill[NE];
__device__ int    g_off[NE];
__device__ int    g_tok[MAXROWS];
__device__ int    g_pair[MAXROWS];
__device__ float  g_gateS[MAXROWS];
__device__ int    g_texp[MAXTILES];

__device__ __forceinline__ float gelu_exact(float v) { return v * normcdff(v); }

__device__ __forceinline__ void cp16(void* dst, const void* src) {
    unsigned d = (unsigned)__cvta_generic_to_shared(dst);
    asm volatile("cp.async.cg.shared.global [%0], [%1], 16;\n" ::"r"(d), "l"(src));
}

__device__ __forceinline__ void ldm_x4(uint32_t* r, uint32_t saddr) {
    asm volatile("ldmatrix.sync.aligned.m8n8.x4.shared.b16 {%0,%1,%2,%3}, [%4];"
                 : "=r"(r[0]), "=r"(r[1]), "=r"(r[2]), "=r"(r[3]) : "r"(saddr));
}

__device__ __forceinline__ void mma16n8k16(float* d, const uint32_t* a, const uint32_t* b) {
    asm volatile(
        "mma.sync.aligned.m16n8k16.row.col.f32.f16.f16.f32 "
        "{%0,%1,%2,%3}, {%4,%5,%6,%7}, {%8,%9}, {%0,%1,%2,%3};\n"
        : "+f"(d[0]), "+f"(d[1]), "+f"(d[2]), "+f"(d[3])
        : "r"(a[0]), "r"(a[1]), "r"(a[2]), "r"(a[3]), "r"(b[0]), "r"(b[1]));
}

// ---------------------------------------------------------------------------
// Kernel 0: fp32 [R][C] -> half transposed [C][R], per expert (blockIdx.z)
// ---------------------------------------------------------------------------
__global__ void transpose_h_kernel(const float* __restrict__ src,
                                   __half* __restrict__ dst, int R, int C) {
    __shared__ float tile[32][33];
    const float* s = src + (size_t)blockIdx.z * R * C;
    __half* d = dst + (size_t)blockIdx.z * R * C;
    int c0 = blockIdx.x * 32, r0 = blockIdx.y * 32;
    int tx = threadIdx.x, ty = threadIdx.y;  // (32, 8)
#pragma unroll
    for (int j = 0; j < 4; j++)
        tile[ty + j * 8][tx] = s[(size_t)(r0 + ty + j * 8) * C + c0 + tx];
    __syncthreads();
#pragma unroll
    for (int j = 0; j < 4; j++)
        d[(size_t)(c0 + ty + j * 8) * R + r0 + tx] =
            __float2half_rn(tile[tx][ty + j * 8]);
}

// ---------------------------------------------------------------------------
// Kernel 1: LayerNorm + router logits + top-4 softmax; writes half xn
// ---------------------------------------------------------------------------
__global__ void ln_router_kernel(const float* __restrict__ x,
                                 const float* __restrict__ gamma,
                                 const float* __restrict__ beta,
                                 const float* __restrict__ rw,
                                 const float* __restrict__ rb) {
    const int t = blockIdx.x;
    const int tid = threadIdx.x;  // 128
    const float* xr = x + (size_t)t * D_DIM;

    float v[8];
    float s = 0.f, ss = 0.f;
#pragma unroll
    for (int i = 0; i < 8; i++) {
        float val = xr[tid + (i << 7)];
        v[i] = val; s += val; ss += val * val;
    }
#pragma unroll
    for (int o = 16; o > 0; o >>= 1) {
        s += __shfl_down_sync(0xffffffffu, s, o);
        ss += __shfl_down_sync(0xffffffffu, ss, o);
    }
    __shared__ float wsum[4], wssq[4];
    if ((tid & 31) == 0) { wsum[tid >> 5] = s; wssq[tid >> 5] = ss; }
    __syncthreads();
    float stot = wsum[0] + wsum[1] + wsum[2] + wsum[3];
    float sstot = wssq[0] + wssq[1] + wssq[2] + wssq[3];
    const float mu = stot * (1.f / D_DIM);
    const float var = sstot * (1.f / D_DIM) - mu * mu;
    const float rstd = rsqrtf(var + 1e-5f);

    float lg[NE];
#pragma unroll
    for (int e = 0; e < NE; e++) lg[e] = 0.f;
    __half* xnout = g_xnh + (size_t)t * D_DIM;
#pragma unroll
    for (int i = 0; i < 8; i++) {
        int idx = tid + (i << 7);
        float xn = (v[i] - mu) * rstd * gamma[idx] + beta[idx];
        xnout[idx] = __float2half_rn(xn);  // GEMM operand
        const float* w = rw + (size_t)idx * NE;
#pragma unroll
        for (int e = 0; e < NE; e++) lg[e] += xn * w[e];  // fp32 routing
    }

    __shared__ float sl[128 * NE];
#pragma unroll
    for (int e = 0; e < NE; e++) sl[tid * NE + e] = lg[e];
    __syncthreads();
    for (int st = 64; st > 0; st >>= 1) {
        if (tid < st) {
#pragma unroll
            for (int e = 0; e < NE; e++) sl[tid * NE + e] += sl[(tid + st) * NE + e];
        }
        __syncthreads();
    }

    if (tid == 0) {
        float logit[NE];
#pragma unroll
        for (int e = 0; e < NE; e++) logit[e] = sl[e] + rb[e];
        int sel[TOPK]; float mv[TOPK]; bool used[NE];
#pragma unroll
        for (int e = 0; e < NE; e++) used[e] = false;
#pragma unroll
        for (int k = 0; k < TOPK; k++) {
            int bi = 0; float bv = -3.4e38f;
#pragma unroll
            for (int e = 0; e < NE; e++)
                if (!used[e] && logit[e] > bv) { bv = logit[e]; bi = e; }
            used[bi] = true; sel[k] = bi; mv[k] = bv;
        }
        const float m = mv[0];
        float den = 0.f, ex[TOPK];
#pragma unroll
        for (int k = 0; k < TOPK; k++) { ex[k] = expf(mv[k] - m); den += ex[k]; }
#pragma unroll
        for (int k = 0; k < TOPK; k++) {
            g_sel[t * TOPK + k]  = sel[k];
            g_gval[t * TOPK + k] = ex[k] / den;
        }
    }
}

// ---------------------------------------------------------------------------
// Kernels 2-4: count / offsets / scatter
// ---------------------------------------------------------------------------
__global__ void count_kernel() {
    __shared__ int hist[NE];
    const int tid = threadIdx.x;  // 512
    if (tid < NE) hist[tid] = 0;
    __syncthreads();
    int i = blockIdx.x * 512 + tid;
    if (i < NPAIR) atomicAdd(&hist[g_sel[i]], 1);
    __syncthreads();
    if (tid < NE) atomicAdd(&g_cnt[tid], hist[tid]);
}

__global__ void offsets_kernel() {
    int off = 0, tile = 0;
    for (int e = 0; e < NE; e++) {
        g_off[e] = off;
        int tiles_e = (g_cnt[e] + 127) >> 7;
        for (int i = 0; i < tiles_e; i++) g_texp[tile++] = e;
        off += tiles_e << 7;
    }
    for (; tile < MAXTILES; tile++) g_texp[tile] = -1;
}

__global__ void scatter_kernel() {
    __shared__ int lcnt[NE], lbase[NE];
    const int tid = threadIdx.x;  // 128
    const int t = blockIdx.x * 128 + tid;
    if (tid < NE) lcnt[tid] = 0;
    __syncthreads();
    int myidx[TOPK], mye[TOPK]; float myg[TOPK];
#pragma unroll
    for (int k = 0; k < TOPK; k++) {
        int e = g_sel[t * TOPK + k];
        mye[k] = e;
        myg[k] = g_gval[t * TOPK + k];
        myidx[k] = atomicAdd(&lcnt[e], 1);
    }
    __syncthreads();
    if (tid < NE) lbase[tid] = atomicAdd(&g_fill[tid], lcnt[tid]);
    __syncthreads();
#pragma unroll
    for (int k = 0; k < TOPK; k++) {
        int pos = g_off[mye[k]] + lbase[mye[k]] + myidx[k];
        g_tok[pos]   = t;
        g_pair[pos]  = t * TOPK + k;
        g_gateS[pos] = myg[k];
    }
}

// ---------------------------------------------------------------------------
// Kernel 5: fp16 GEMM via mma.m16n8k16 + ldmatrix, 128x128x32 CTA tile,
// 4 warps (2x2), warp 64x64. B pre-transposed n-major [N][K].
//   isGemm1: A gathered from g_xnh via g_tok; Out(half) = gelu(A@B + b1)
//   else   : A = g_hh contiguous;  g_yp[pair] = (A@B + b2) * gate  (fp32)
// ---------------------------------------------------------------------------
__global__ __launch_bounds__(128, 2) void moe_gemm_h(
    const __half* __restrict__ A, const __half* __restrict__ B,
    const float* __restrict__ bias, void* __restrict__ Out,
    int K, int N, int isGemm1) {
    extern __shared__ __half smh[];
    __shared__ int   stok[128];
    __shared__ float sgate[128];
    __half* sAbuf[2] = {smh, smh + STAGE_H};
    __half* sBbuf[2] = {smh + 128 * LDAH, smh + STAGE_H + 128 * LDAH};

    const int tid = threadIdx.x;     // 128
    const int warp = tid >> 5;
    const int lane = tid & 31;
    const int tig = lane & 3;
    const int wm = warp >> 1;        // 0..1
    const int wn = warp & 1;         // 0..1
    const int te = g_texp[blockIdx.y];
    if (te < 0) return;
    const int r0 = blockIdx.y * 128;
    const int n0 = blockIdx.x * 128;
    const __half* Bp = B + (size_t)te * K * N;   // [N][K] n-major
    const float* biasp = bias + (size_t)te * N;

    if (isGemm1) {
        stok[tid] = g_tok[r0 + tid];
        __syncthreads();
    }

    // staging: rows (tid>>2)+32j, col-chunk (tid&3)*8 halves (16B)
    const int srow = tid >> 2, sc8 = (tid & 3) * 8;
    const __half* asrc[4];
#pragma unroll
    for (int j = 0; j < 4; j++) {
        int r = srow + j * 32;
        if (isGemm1) {
            int tk = stok[r]; if (tk < 0) tk = 0;
            asrc[j] = g_xnh + (size_t)tk * D_DIM + sc8;
        } else {
            asrc[j] = A + (size_t)(r0 + r) * K + sc8;
        }
    }
    const __half* bsrc[4];
#pragma unroll
    for (int j = 0; j < 4; j++) {
        int r = srow + j * 32;
        bsrc[j] = Bp + (size_t)(n0 + r) * K + sc8;
    }

    float acc[4][8][4];
#pragma unroll
    for (int mi = 0; mi < 4; mi++)
#pragma unroll
        for (int ni = 0; ni < 8; ni++)
#pragma unroll
            for (int q = 0; q < 4; q++) acc[mi][ni][q] = 0.f;

    // ldmatrix lane address components
    const uint32_t sA0 = (uint32_t)__cvta_generic_to_shared(smh);
    const int a_lr = (lane & 7) + ((lane >> 3) & 1) * 8;   // row within 16
    const int a_lc = ((lane >> 4) & 1) * 8;                // k within 16
    const int b_lr = (lane & 7) + ((lane >> 4) & 1) * 8;   // n within 16
    const int b_lc = ((lane >> 3) & 1) * 8;                // k within 16

    const int ktiles = K >> 5;

#define STAGE(s, kt)                                                   \
    do {                                                               \
        __half* sa_ = sAbuf[s]; __half* sb_ = sBbuf[s];                \
        _Pragma("unroll")                                              \
        for (int j = 0; j < 4; j++) {                                  \
            int r = srow + j * 32;                                     \
            cp16(sa_ + r * LDAH + sc8, asrc[j] + (kt) * 32);           \
            cp16(sb_ + r * LDAH + sc8, bsrc[j] + (kt) * 32);           \
        }                                                              \
        asm volatile("cp.async.commit_group;\n");                      \
    } while (0)

    STAGE(0, 0);
    for (int kt = 0; kt < ktiles; kt++) {
        int s = kt & 1;
        if (kt + 1 < ktiles) {
            STAGE(s ^ 1, kt + 1);
            asm volatile("cp.async.wait_group 1;\n");
        } else {
            asm volatile("cp.async.wait_group 0;\n");
        }
        __syncthreads();

        const uint32_t sAu = sA0 + (uint32_t)(s * STAGE_H) * 2u;
        const uint32_t sBu = sAu + (uint32_t)(128 * LDAH) * 2u;
#pragma unroll
        for (int ks = 0; ks < 2; ks++) {
            uint32_t afr[4][4];
#pragma unroll
            for (int mi = 0; mi < 4; mi++)
                ldm_x4(afr[mi],
                       sAu + (uint32_t)(((wm * 64 + mi * 16 + a_lr) * LDAH +
                                         ks * 16 + a_lc) * 2));
            uint32_t bfr[8][2];
#pragma unroll
            for (int np = 0; np < 4; np++) {
                uint32_t tmp[4];
                ldm_x4(tmp,
                       sBu + (uint32_t)(((wn * 64 + np * 16 + b_lr) * LDAH +
                                         ks * 16 + b_lc) * 2));
                bfr[2 * np][0] = tmp[0]; bfr[2 * np][1] = tmp[1];
                bfr[2 * np + 1][0] = tmp[2]; bfr[2 * np + 1][1] = tmp[3];
            }
#pragma unroll
            for (int mi = 0; mi < 4; mi++)
#pragma unroll
                for (int ni = 0; ni < 8; ni++)
                    mma16n8k16(acc[mi][ni], afr[mi], bfr[ni]);
        }
        __syncthreads();
    }
#undef STAGE

    if (!isGemm1) {
        stok[tid]  = g_pair[r0 + tid];
        sgate[tid] = g_gateS[r0 + tid];
    }

    // epilogue: two 64-row phases via smem fp32 (64 x 132)
    float* sC = (float*)smh;
    const int gid = lane >> 2;
    for (int p = 0; p < 2; p++) {
        if (wm == p) {
#pragma unroll
            for (int mi = 0; mi < 4; mi++)
#pragma unroll
                for (int ni = 0; ni < 8; ni++) {
                    int rr = mi * 16 + gid;
                    int cc = wn * 64 + ni * 8 + 2 * tig;
                    sC[rr * 132 + cc]           = acc[mi][ni][0];
                    sC[rr * 132 + cc + 1]       = acc[mi][ni][1];
                    sC[(rr + 8) * 132 + cc]     = acc[mi][ni][2];
                    sC[(rr + 8) * 132 + cc + 1] = acc[mi][ni][3];
                }
        }
        __syncthreads();
#pragma unroll
        for (int j = 0; j < 16; j++) {
            int f = tid + j * 128;               // 2048 float4s = 64x128
            int r = f >> 5, c = (f & 31) << 2;
            int lrow = p * 64 + r;
            int gn = n0 + c;
            float4 cv = *(float4*)(sC + r * 132 + c);
            float4 bv = *(const float4*)(biasp + gn);
            if (isGemm1) {
                __half2 h0 = __floats2half2_rn(gelu_exact(cv.x + bv.x),
                                               gelu_exact(cv.y + bv.y));
                __half2 h1 = __floats2half2_rn(gelu_exact(cv.z + bv.z),
                                               gelu_exact(cv.w + bv.w));
                uint2 pk;
                pk.x = *(uint32_t*)&h0;
                pk.y = *(uint32_t*)&h1;
                *(uint2*)((__half*)Out + (size_t)(r0 + lrow) * N + gn) = pk;
            } else {
                int pair = stok[lrow];
                if (pair >= 0) {
                    float g = sgate[lrow];
                    float4 ov;
                    ov.x = (cv.x + bv.x) * g;
                    ov.y = (cv.y + bv.y) * g;
                    ov.z = (cv.z + bv.z) * g;
                    ov.w = (cv.w + bv.w) * g;
                    *(float4*)((float*)Out + (size_t)pair * N + gn) = ov;
                }
            }
        }
        __syncthreads();
    }
}

// ---------------------------------------------------------------------------
// Kernel 6: combine 4 pair contributions per token (fixed order)
// ---------------------------------------------------------------------------
__global__ void combine_kernel(float* __restrict__ y) {
    const int i = blockIdx.x * 256 + threadIdx.x;
    const int t = i >> 8;
    const int c = i & 255;
    const float4* yp4 = (const float4*)g_yp;
    size_t bidx = (size_t)t * TOPK * 256 + c;
    float4 a = yp4[bidx];
    float4 b = yp4[bidx + 256];
    float4 d = yp4[bidx + 512];
    float4 e = yp4[bidx + 768];
    float4 s;
    s.x = a.x + b.x + d.x + e.x;
    s.y = a.y + b.y + d.y + e.y;
    s.z = a.z + b.z + d.z + e.z;
    s.w = a.w + b.w + d.w + e.w;
    ((float4*)y)[i] = s;
}

// ---------------------------------------------------------------------------
extern "C" void kernel_launch(void* const* d_in, const int* in_sizes, int n_in,
                              void* d_out, int out_size) {
    const float* x     = (const float*)d_in[0];
    const float* gamma = (const float*)d_in[1];
    const float* beta  = (const float*)d_in[2];
    const float* rw    = (const float*)d_in[3];
    const float* rb    = (const float*)d_in[4];
    const float* w1    = (const float*)d_in[5];
    const float* b1    = (const float*)d_in[6];
    const float* w2    = (const float*)d_in[7];
    const float* b2    = (const float*)d_in[8];
    float* y = (float*)d_out;

    __half *xnh_p = nullptr, *hh_p = nullptr, *w1t_p = nullptr, *w2t_p = nullptr;
    float* yp_p = nullptr;
    int *cnt_p = nullptr, *fill_p = nullptr, *tok_p = nullptr, *pair_p = nullptr;
    cudaGetSymbolAddress((void**)&xnh_p, g_xnh);
    cudaGetSymbolAddress((void**)&hh_p, g_hh);
    cudaGetSymbolAddress((void**)&yp_p, g_yp);
    cudaGetSymbolAddress((void**)&w1t_p, g_w1t);
    cudaGetSymbolAddress((void**)&w2t_p, g_w2t);
    cudaGetSymbolAddress((void**)&cnt_p, g_cnt);
    cudaGetSymbolAddress((void**)&fill_p, g_fill);
    cudaGetSymbolAddress((void**)&tok_p, g_tok);
    cudaGetSymbolAddress((void**)&pair_p, g_pair);

    cudaFuncSetAttribute(moe_gemm_h,
                         cudaFuncAttributeMaxDynamicSharedMemorySize, GEMM_SMEM);

    cudaMemsetAsync(cnt_p, 0, NE * sizeof(int));
    cudaMemsetAsync(fill_p, 0, NE * sizeof(int));
    cudaMemsetAsync(tok_p, 0xFF, MAXROWS * sizeof(int));
    cudaMemsetAsync(pair_p, 0xFF, MAXROWS * sizeof(int));

    // weights: fp32 [E][K][N] -> half transposed [E][N][K]
    dim3 tb(32, 8);
    transpose_h_kernel<<<dim3(H_DIM / 32, D_DIM / 32, NE), tb>>>(w1, w1t_p, D_DIM, H_DIM);
    transpose_h_kernel<<<dim3(O_DIM / 32, H_DIM / 32, NE), tb>>>(w2, w2t_p, H_DIM, O_DIM);

    ln_router_kernel<<<T_TOK, 128>>>(x, gamma, beta, rw, rb);
    count_kernel<<<(NPAIR + 511) / 512, 512>>>();
    offsets_kernel<<<1, 1>>>();
    scatter_kernel<<<T_TOK / 128, 128>>>();

    dim3 g1(H_DIM / 128, MAXTILES);
    dim3 g2(O_DIM / 128, MAXTILES);
    moe_gemm_h<<<g1, 128, GEMM_SMEM>>>(xnh_p, w1t_p, b1, hh_p, D_DIM, H_DIM, 1);
    moe_gemm_h<<<g2, 128, GEMM_SMEM>>>(hh_p, w2t_p, b2, yp_p, H_DIM, O_DIM, 0);

    combine_kernel<<<(T_TOK * O_DIM / 4) / 256, 256>>>(y);
}